// round 11
// baseline (speedup 1.0000x reference)
#include <cuda_runtime.h>
#include <cstdint>

// MultiHeadAttention_5128190951704 — algebraic collapse:
//   softmax rows sum to 1 and the 'bnqk,bnvd->bnqd' einsum is separable in k/v,
//   so   y[b,o,d] = b_proj[o] + sum_n wp_sum[o,n] * sum_c wv_sum[n,c] * x[b,c,d]
// i.e. a rank-8 channel map per spatial position. Memory-bound: 256 MB traffic.

#define B_   16
#define C_   512
#define NH_  8
#define S_   4096          // H*W
#define TPB  128           // threads per block
#define POS_PER_BLOCK 256  // 2 positions (one f32x2) per thread

typedef unsigned long long ull;

// Scratch for folded weights (alloc-free rule: __device__ globals)
__device__ float g_wv[NH_ * C_];  // [n][c]  = sum of 64 V-rows of w_qkv per head
__device__ float g_wp[C_ * NH_];  // [o][n]  = sum of 64 proj columns per head

__device__ __forceinline__ ull dup2(float v) {
    ull r;
    asm("mov.b64 %0, {%1, %1};" : "=l"(r) : "r"(__float_as_uint(v)));
    return r;
}
__device__ __forceinline__ ull fma2(ull a, ull b, ull c) {
    ull d;
    asm("fma.rn.f32x2 %0, %1, %2, %3;" : "=l"(d) : "l"(a), "l"(b), "l"(c));
    return d;
}

// ---------------------------------------------------------------------------
// Prep: fold weights. 8192 outputs, each a 64-term sum. ~1 MB reads, trivial.
// ---------------------------------------------------------------------------
__global__ void prep_kernel(const float* __restrict__ wqkv,
                            const float* __restrict__ wproj) {
    int t = blockIdx.x * blockDim.x + threadIdx.x;
    if (t < NH_ * C_) {
        // wv_sum[n][c] = sum_j wqkv[2C + n*64 + j][c]
        int n = t >> 9, c = t & (C_ - 1);
        const float* p = wqkv + (size_t)(2 * C_ + n * 64) * C_ + c;
        float s = 0.f;
        #pragma unroll
        for (int j = 0; j < 64; j++) s += p[(size_t)j * C_];
        g_wv[n * C_ + c] = s;
    } else if (t < 2 * NH_ * C_) {
        // wp_sum[o][n] = sum_j wproj[o][n*64 + j]
        int u = t - NH_ * C_;
        int o = u >> 3, n = u & 7;
        const float* p = wproj + (size_t)o * C_ + n * 64;
        float s = 0.f;
        #pragma unroll
        for (int j = 0; j < 64; j++) s += p[j];
        g_wp[o * NH_ + n] = s;
    }
}

// ---------------------------------------------------------------------------
// Main fused kernel. Block = 128 threads x 2 positions (packed f32x2).
// Grid = 16 batches x 16 spatial tiles = 256 blocks.
// SMEM: duplicated-packed weights for FFMA2 (broadcast LDS, conflict-free).
//   s_wv2 [c][n] 32 KB | s_wp2 [o][n] 32 KB | s_b2 [o] 4 KB  = 68 KB dynamic.
// ---------------------------------------------------------------------------
#define SMEM_BYTES ((NH_ * C_ + C_ * NH_ + C_) * 8)  // 69632

__global__ void __launch_bounds__(TPB)
attn_main(const float* __restrict__ x,
          const float* __restrict__ bias,
          float* __restrict__ y) {
    extern __shared__ ull smem[];
    ull* s_wv2 = smem;                 // [c][n], c-major so per-c weights are contiguous
    ull* s_wp2 = smem + NH_ * C_;      // [o][n]
    ull* s_b2  = smem + 2 * NH_ * C_;  // [o]

    const int tid = threadIdx.x;
    for (int t = tid; t < NH_ * C_; t += TPB) {
        int c = t >> 3, n = t & 7;
        s_wv2[t] = dup2(g_wv[n * C_ + c]);  // transpose [n][c] -> [c][n]
        s_wp2[t] = dup2(g_wp[t]);
    }
    for (int t = tid; t < C_; t += TPB) s_b2[t] = dup2(bias[t]);
    __syncthreads();

    const int b     = blockIdx.x >> 4;
    const int tile  = blockIdx.x & 15;
    const int dbase = tile * POS_PER_BLOCK;

    // ---- Phase 1: acc[n] = sum_c wv_sum[n,c] * x[b,c,d0..d1]  (packed pair)
    const ull* xp = (const ull*)(x + (size_t)b * C_ * S_ + dbase) + tid;
    ull acc[NH_];
    #pragma unroll
    for (int n = 0; n < NH_; n++) acc[n] = 0ull;

    #pragma unroll 4
    for (int c = 0; c < C_; c++) {
        ull xv = xp[(size_t)c * (S_ / 2)];  // coalesced 8B/thread
        const ulonglong2* wv = (const ulonglong2*)(s_wv2 + c * 8);
        ulonglong2 w0 = wv[0], w1 = wv[1], w2 = wv[2], w3 = wv[3];
        acc[0] = fma2(w0.x, xv, acc[0]);
        acc[1] = fma2(w0.y, xv, acc[1]);
        acc[2] = fma2(w1.x, xv, acc[2]);
        acc[3] = fma2(w1.y, xv, acc[3]);
        acc[4] = fma2(w2.x, xv, acc[4]);
        acc[5] = fma2(w2.y, xv, acc[5]);
        acc[6] = fma2(w3.x, xv, acc[6]);
        acc[7] = fma2(w3.y, xv, acc[7]);
    }

    // ---- Phase 2: y[b,o,d] = b[o] + sum_n wp_sum[o,n] * acc[n]
    ull* yp = (ull*)(y + (size_t)b * C_ * S_ + dbase) + tid;
    #pragma unroll 2
    for (int o = 0; o < C_; o++) {
        ull r = s_b2[o];
        const ulonglong2* wp = (const ulonglong2*)(s_wp2 + o * 8);
        ulonglong2 w0 = wp[0], w1 = wp[1], w2 = wp[2], w3 = wp[3];
        r = fma2(w0.x, acc[0], r);
        r = fma2(w0.y, acc[1], r);
        r = fma2(w1.x, acc[2], r);
        r = fma2(w1.y, acc[3], r);
        r = fma2(w2.x, acc[4], r);
        r = fma2(w2.y, acc[5], r);
        r = fma2(w3.x, acc[6], r);
        r = fma2(w3.y, acc[7], r);
        yp[(size_t)o * (S_ / 2)] = r;   // coalesced STG.64
    }
}

// ---------------------------------------------------------------------------
extern "C" void kernel_launch(void* const* d_in, const int* in_sizes, int n_in,
                              void* d_out, int out_size) {
    const float* x     = (const float*)d_in[0];
    const float* wqkv  = (const float*)d_in[1];
    const float* wproj = (const float*)d_in[2];
    const float* bproj = (const float*)d_in[3];
    float* y = (float*)d_out;

    cudaFuncSetAttribute(attn_main, cudaFuncAttributeMaxDynamicSharedMemorySize,
                         SMEM_BYTES);

    prep_kernel<<<32, 256>>>(wqkv, wproj);
    attn_main<<<B_ * (S_ / POS_PER_BLOCK), TPB, SMEM_BYTES>>>(x, bproj, y);
}

// round 12
// speedup vs baseline: 2.1237x; 2.1237x over previous
#include <cuda_runtime.h>
#include <cstdint>

// MultiHeadAttention_5128190951704 — algebraic collapse:
//   softmax rows sum to 1 and 'bnqk,bnvd->bnqd' is separable in k/v, so
//   y[b,o,d] = b_proj[o] + sum_n wp_sum[o,n] * sum_c wv_sum[n,c] * x[b,c,d]
// Rank-8 channel map per position. Memory-bound: 256 MB ideal traffic.
//
// R11 restructure: c-split across 4 groups per block for 4x occupancy + MLP.

#define B_   16
#define C_   512
#define NH_  8
#define S_   4096          // H*W
#define TPB  256
#define G_   4             // channel groups per block
#define GSZ  64            // threads per group
#define P_   128           // positions per block (2 per thread)
#define CPG  128           // channels per group
#define REDP 10            // padded reduction row (ulls): 80B, LDS.128-aligned, conflict-free

typedef unsigned long long ull;

// Folded weights (alloc-free rule: __device__ globals)
__device__ ull   g_wv2[C_ * NH_];   // [c][n], value duplicated into both f32 halves
__device__ float g_wp [C_ * NH_];   // [o][n]

__device__ __forceinline__ ull dup2(float v) {
    ull r;
    asm("mov.b64 %0, {%1, %1};" : "=l"(r) : "r"(__float_as_uint(v)));
    return r;
}
__device__ __forceinline__ ull fma2(ull a, ull b, ull c) {
    ull d;
    asm("fma.rn.f32x2 %0, %1, %2, %3;" : "=l"(d) : "l"(a), "l"(b), "l"(c));
    return d;
}
__device__ __forceinline__ ull add2(ull a, ull b) {
    ull d;
    asm("add.rn.f32x2 %0, %1, %2;" : "=l"(d) : "l"(a), "l"(b));
    return d;
}

// ---------------------------------------------------------------------------
// Prep: fold weights (8192 sums of 64 terms, ~1 MB reads, trivial cost).
// ---------------------------------------------------------------------------
__global__ void prep_kernel(const float* __restrict__ wqkv,
                            const float* __restrict__ wproj) {
    int t = blockIdx.x * blockDim.x + threadIdx.x;
    if (t < NH_ * C_) {
        // wv_sum[n][c] = sum_j wqkv[2C + n*64 + j][c], stored [c][n] dup'd
        int n = t >> 9, c = t & (C_ - 1);
        const float* p = wqkv + (size_t)(2 * C_ + n * 64) * C_ + c;
        float s = 0.f;
        #pragma unroll
        for (int j = 0; j < 64; j++) s += p[(size_t)j * C_];
        g_wv2[c * NH_ + n] = dup2(s);
    } else if (t < 2 * NH_ * C_) {
        // wp_sum[o][n] = sum_j wproj[o][n*64 + j]
        int u = t - NH_ * C_;
        int o = u >> 3, n = u & 7;
        const float* p = wproj + (size_t)o * C_ + n * 64;
        float s = 0.f;
        #pragma unroll
        for (int j = 0; j < 64; j++) s += p[j];
        g_wp[o * NH_ + n] = s;
    }
}

// ---------------------------------------------------------------------------
// Main kernel: 512 blocks x 256 threads.
// Group g (64 threads) phase1: channels [g*128, g*128+128) of the block's
// 128 positions; SMEM reduction of the 8 packed accumulators; phase2:
// output channels [g*128, g*128+128).
// SMEM: wv2 32KB | red 20KB | wp 16KB | bias 2KB = 70KB -> 3 CTAs/SM.
// ---------------------------------------------------------------------------
#define SMEM_ULLS  (C_ * NH_ + G_ * GSZ * REDP)          // 4096 + 2560
#define SMEM_BYTES (SMEM_ULLS * 8 + (C_ * NH_ + C_) * 4) // 71680

__global__ void __launch_bounds__(TPB, 3)
attn_main(const float* __restrict__ x,
          const float* __restrict__ bias,
          float* __restrict__ y) {
    extern __shared__ ull smem[];
    ull*   s_wv2 = smem;                         // [c][n] packed, 4096 ull
    ull*   s_red = smem + C_ * NH_;              // [g][tg][n(+pad)], 2560 ull
    float* s_wp  = (float*)(smem + SMEM_ULLS);   // [o][n], 4096 f
    float* s_b   = s_wp + C_ * NH_;              // [o], 512 f

    const int tid = threadIdx.x;
    for (int t = tid; t < C_ * NH_; t += TPB) {
        s_wv2[t] = g_wv2[t];
        s_wp[t]  = g_wp[t];
    }
    for (int t = tid; t < C_; t += TPB) s_b[t] = bias[t];
    __syncthreads();

    const int b     = blockIdx.x >> 5;           // 16 batches
    const int tile  = blockIdx.x & 31;           // 32 tiles of 128 positions
    const int dhalf = (tile * P_) >> 1;          // pair-index base
    const int g     = tid >> 6;                  // channel/output group
    const int tg    = tid & (GSZ - 1);           // position-pair owner

    // ---- Phase 1: partial acc over this group's 128 channels ----
    const ull* xp = (const ull*)x + (size_t)(b * C_ + g * CPG) * (S_ / 2)
                    + dhalf + tg;
    ull acc[NH_];
    #pragma unroll
    for (int n = 0; n < NH_; n++) acc[n] = 0ull;

    #pragma unroll 8
    for (int cc = 0; cc < CPG; cc++) {
        ull xv = xp[(size_t)cc * (S_ / 2)];      // coalesced, 8 in flight
        const ulonglong2* wv =
            (const ulonglong2*)(s_wv2 + (g * CPG + cc) * NH_);
        ulonglong2 w0 = wv[0], w1 = wv[1], w2 = wv[2], w3 = wv[3];
        acc[0] = fma2(w0.x, xv, acc[0]);
        acc[1] = fma2(w0.y, xv, acc[1]);
        acc[2] = fma2(w1.x, xv, acc[2]);
        acc[3] = fma2(w1.y, xv, acc[3]);
        acc[4] = fma2(w2.x, xv, acc[4]);
        acc[5] = fma2(w2.y, xv, acc[5]);
        acc[6] = fma2(w3.x, xv, acc[6]);
        acc[7] = fma2(w3.y, xv, acc[7]);
    }

    // ---- Cross-group reduction through padded SMEM ----
    {
        ull* r = s_red + (g * GSZ + tg) * REDP;
        #pragma unroll
        for (int n = 0; n < NH_; n += 2)
            *(ulonglong2*)(r + n) = make_ulonglong2(acc[n], acc[n + 1]);
    }
    __syncthreads();

    ull tot[NH_];
    #pragma unroll
    for (int n = 0; n < NH_; n++) tot[n] = 0ull;
    #pragma unroll
    for (int gg = 0; gg < G_; gg++) {
        const ull* r = s_red + (gg * GSZ + tg) * REDP;
        #pragma unroll
        for (int n = 0; n < NH_; n += 2) {
            ulonglong2 v = *(const ulonglong2*)(r + n);
            tot[n]     = add2(tot[n], v.x);
            tot[n + 1] = add2(tot[n + 1], v.y);
        }
    }

    // ---- Phase 2: this group's 128 output channels ----
    ull* yp = (ull*)y + (size_t)(b * C_ + g * CPG) * (S_ / 2) + dhalf + tg;
    #pragma unroll 4
    for (int oo = 0; oo < CPG; oo++) {
        const int o = g * CPG + oo;
        const float4* wp = (const float4*)(s_wp + o * NH_);
        float4 wa = wp[0], wb = wp[1];
        ull r = dup2(s_b[o]);
        r = fma2(dup2(wa.x), tot[0], r);
        r = fma2(dup2(wa.y), tot[1], r);
        r = fma2(dup2(wa.z), tot[2], r);
        r = fma2(dup2(wa.w), tot[3], r);
        r = fma2(dup2(wb.x), tot[4], r);
        r = fma2(dup2(wb.y), tot[5], r);
        r = fma2(dup2(wb.z), tot[6], r);
        r = fma2(dup2(wb.w), tot[7], r);
        yp[(size_t)oo * (S_ / 2)] = r;           // coalesced STG.64
    }
}

// ---------------------------------------------------------------------------
extern "C" void kernel_launch(void* const* d_in, const int* in_sizes, int n_in,
                              void* d_out, int out_size) {
    const float* x     = (const float*)d_in[0];
    const float* wqkv  = (const float*)d_in[1];
    const float* wproj = (const float*)d_in[2];
    const float* bproj = (const float*)d_in[3];
    float* y = (float*)d_out;

    cudaFuncSetAttribute(attn_main, cudaFuncAttributeMaxDynamicSharedMemorySize,
                         SMEM_BYTES);

    prep_kernel<<<32, 256>>>(wqkv, wproj);
    attn_main<<<B_ * (S_ / P_), TPB, SMEM_BYTES>>>(x, bproj, y);
}

// round 13
// speedup vs baseline: 2.1671x; 1.0205x over previous
#include <cuda_runtime.h>
#include <cstdint>

// MultiHeadAttention_5128190951704 — algebraic collapse:
//   softmax rows sum to 1 and 'bnqk,bnvd->bnqd' is separable in k/v, so
//   y[b,o,d] = b_proj[o] + sum_n wp_sum[o,n] * sum_c wv_sum[n,c] * x[b,c,d]
// Rank-8 channel map per position. Memory-bound: 256 MB ideal traffic.
//
// R11 restructure: c-split across 4 groups per block for 4x occupancy + MLP.

#define B_   16
#define C_   512
#define NH_  8
#define S_   4096          // H*W
#define TPB  256
#define G_   4             // channel groups per block
#define GSZ  64            // threads per group
#define P_   128           // positions per block (2 per thread)
#define CPG  128           // channels per group
#define REDP 10            // padded reduction row (ulls): 80B, LDS.128-aligned, conflict-free

typedef unsigned long long ull;

// Folded weights (alloc-free rule: __device__ globals)
__device__ ull   g_wv2[C_ * NH_];   // [c][n], value duplicated into both f32 halves
__device__ float g_wp [C_ * NH_];   // [o][n]

__device__ __forceinline__ ull dup2(float v) {
    ull r;
    asm("mov.b64 %0, {%1, %1};" : "=l"(r) : "r"(__float_as_uint(v)));
    return r;
}
__device__ __forceinline__ ull fma2(ull a, ull b, ull c) {
    ull d;
    asm("fma.rn.f32x2 %0, %1, %2, %3;" : "=l"(d) : "l"(a), "l"(b), "l"(c));
    return d;
}
__device__ __forceinline__ ull add2(ull a, ull b) {
    ull d;
    asm("add.rn.f32x2 %0, %1, %2;" : "=l"(d) : "l"(a), "l"(b));
    return d;
}

// ---------------------------------------------------------------------------
// Prep: fold weights (8192 sums of 64 terms, ~1 MB reads, trivial cost).
// ---------------------------------------------------------------------------
__global__ void prep_kernel(const float* __restrict__ wqkv,
                            const float* __restrict__ wproj) {
    int t = blockIdx.x * blockDim.x + threadIdx.x;
    if (t < NH_ * C_) {
        // wv_sum[n][c] = sum_j wqkv[2C + n*64 + j][c], stored [c][n] dup'd
        int n = t >> 9, c = t & (C_ - 1);
        const float* p = wqkv + (size_t)(2 * C_ + n * 64) * C_ + c;
        float s = 0.f;
        #pragma unroll
        for (int j = 0; j < 64; j++) s += p[(size_t)j * C_];
        g_wv2[c * NH_ + n] = dup2(s);
    } else if (t < 2 * NH_ * C_) {
        // wp_sum[o][n] = sum_j wproj[o][n*64 + j]
        int u = t - NH_ * C_;
        int o = u >> 3, n = u & 7;
        const float* p = wproj + (size_t)o * C_ + n * 64;
        float s = 0.f;
        #pragma unroll
        for (int j = 0; j < 64; j++) s += p[j];
        g_wp[o * NH_ + n] = s;
    }
}

// ---------------------------------------------------------------------------
// Main kernel: 512 blocks x 256 threads.
// Group g (64 threads) phase1: channels [g*128, g*128+128) of the block's
// 128 positions; SMEM reduction of the 8 packed accumulators; phase2:
// output channels [g*128, g*128+128).
// SMEM: wv2 32KB | red 20KB | wp 16KB | bias 2KB = 70KB -> 3 CTAs/SM.
// ---------------------------------------------------------------------------
#define SMEM_ULLS  (C_ * NH_ + G_ * GSZ * REDP)          // 4096 + 2560
#define SMEM_BYTES (SMEM_ULLS * 8 + (C_ * NH_ + C_) * 4) // 71680

__global__ void __launch_bounds__(TPB, 3)
attn_main(const float* __restrict__ x,
          const float* __restrict__ bias,
          float* __restrict__ y) {
    extern __shared__ ull smem[];
    ull*   s_wv2 = smem;                         // [c][n] packed, 4096 ull
    ull*   s_red = smem + C_ * NH_;              // [g][tg][n(+pad)], 2560 ull
    float* s_wp  = (float*)(smem + SMEM_ULLS);   // [o][n], 4096 f
    float* s_b   = s_wp + C_ * NH_;              // [o], 512 f

    const int tid = threadIdx.x;
    for (int t = tid; t < C_ * NH_; t += TPB) {
        s_wv2[t] = g_wv2[t];
        s_wp[t]  = g_wp[t];
    }
    for (int t = tid; t < C_; t += TPB) s_b[t] = bias[t];
    __syncthreads();

    const int b     = blockIdx.x >> 5;           // 16 batches
    const int tile  = blockIdx.x & 31;           // 32 tiles of 128 positions
    const int dhalf = (tile * P_) >> 1;          // pair-index base
    const int g     = tid >> 6;                  // channel/output group
    const int tg    = tid & (GSZ - 1);           // position-pair owner

    // ---- Phase 1: partial acc over this group's 128 channels ----
    const ull* xp = (const ull*)x + (size_t)(b * C_ + g * CPG) * (S_ / 2)
                    + dhalf + tg;
    ull acc[NH_];
    #pragma unroll
    for (int n = 0; n < NH_; n++) acc[n] = 0ull;

    #pragma unroll 8
    for (int cc = 0; cc < CPG; cc++) {
        ull xv = xp[(size_t)cc * (S_ / 2)];      // coalesced, 8 in flight
        const ulonglong2* wv =
            (const ulonglong2*)(s_wv2 + (g * CPG + cc) * NH_);
        ulonglong2 w0 = wv[0], w1 = wv[1], w2 = wv[2], w3 = wv[3];
        acc[0] = fma2(w0.x, xv, acc[0]);
        acc[1] = fma2(w0.y, xv, acc[1]);
        acc[2] = fma2(w1.x, xv, acc[2]);
        acc[3] = fma2(w1.y, xv, acc[3]);
        acc[4] = fma2(w2.x, xv, acc[4]);
        acc[5] = fma2(w2.y, xv, acc[5]);
        acc[6] = fma2(w3.x, xv, acc[6]);
        acc[7] = fma2(w3.y, xv, acc[7]);
    }

    // ---- Cross-group reduction through padded SMEM ----
    {
        ull* r = s_red + (g * GSZ + tg) * REDP;
        #pragma unroll
        for (int n = 0; n < NH_; n += 2)
            *(ulonglong2*)(r + n) = make_ulonglong2(acc[n], acc[n + 1]);
    }
    __syncthreads();

    ull tot[NH_];
    #pragma unroll
    for (int n = 0; n < NH_; n++) tot[n] = 0ull;
    #pragma unroll
    for (int gg = 0; gg < G_; gg++) {
        const ull* r = s_red + (gg * GSZ + tg) * REDP;
        #pragma unroll
        for (int n = 0; n < NH_; n += 2) {
            ulonglong2 v = *(const ulonglong2*)(r + n);
            tot[n]     = add2(tot[n], v.x);
            tot[n + 1] = add2(tot[n + 1], v.y);
        }
    }

    // ---- Phase 2: this group's 128 output channels ----
    ull* yp = (ull*)y + (size_t)(b * C_ + g * CPG) * (S_ / 2) + dhalf + tg;
    #pragma unroll 4
    for (int oo = 0; oo < CPG; oo++) {
        const int o = g * CPG + oo;
        const float4* wp = (const float4*)(s_wp + o * NH_);
        float4 wa = wp[0], wb = wp[1];
        ull r = dup2(s_b[o]);
        r = fma2(dup2(wa.x), tot[0], r);
        r = fma2(dup2(wa.y), tot[1], r);
        r = fma2(dup2(wa.z), tot[2], r);
        r = fma2(dup2(wa.w), tot[3], r);
        r = fma2(dup2(wb.x), tot[4], r);
        r = fma2(dup2(wb.y), tot[5], r);
        r = fma2(dup2(wb.z), tot[6], r);
        r = fma2(dup2(wb.w), tot[7], r);
        yp[(size_t)oo * (S_ / 2)] = r;           // coalesced STG.64
    }
}

// ---------------------------------------------------------------------------
extern "C" void kernel_launch(void* const* d_in, const int* in_sizes, int n_in,
                              void* d_out, int out_size) {
    const float* x     = (const float*)d_in[0];
    const float* wqkv  = (const float*)d_in[1];
    const float* wproj = (const float*)d_in[2];
    const float* bproj = (const float*)d_in[3];
    float* y = (float*)d_out;

    cudaFuncSetAttribute(attn_main, cudaFuncAttributeMaxDynamicSharedMemorySize,
                         SMEM_BYTES);

    prep_kernel<<<32, 256>>>(wqkv, wproj);
    attn_main<<<B_ * (S_ / P_), TPB, SMEM_BYTES>>>(x, bproj, y);
}